// round 1
// baseline (speedup 1.0000x reference)
#include <cuda_runtime.h>

#define BB   8192
#define CC   2514
#define NN   2513      // number of foreground classes
#define TPB  256
#define P_EXP 0.8f
#define Q_EXP 2.0f
#define LOG_EPS -4.6051701859880914f   // log(0.01)
#define NEG_BIG -1e30f

__device__ int   g_hist[NN];
__device__ int   g_labels[BB];
__device__ float g_lc[NN];
__device__ float g_row_out[BB];

// ---------------------------------------------------------------------------
__global__ void k_zero_hist() {
    int i = blockIdx.x * blockDim.x + threadIdx.x;
    if (i < NN) g_hist[i] = 0;
}

// One block per row: find the one-hot label position, histogram fg labels.
__global__ void k_labels(const float* __restrict__ t) {
    int row = blockIdx.x;
    const float2* tr = reinterpret_cast<const float2*>(t + (size_t)row * CC);
    __shared__ int s_label;
    if (threadIdx.x == 0) s_label = 0;
    __syncthreads();
    // CC = 2514 -> 1257 float2 per row (rows are 8B aligned: 2514*4 % 8 == 0)
    for (int i = threadIdx.x; i < CC / 2; i += TPB) {
        float2 v = tr[i];
        if (v.x > 0.f) s_label = 2 * i;
        if (v.y > 0.f) s_label = 2 * i + 1;
    }
    __syncthreads();
    if (threadIdx.x == 0) {
        int l = s_label;
        g_labels[row] = l;
        if (l > 0) atomicAdd(&g_hist[l - 1], 1);
    }
}

// lc[j] = log(max(cum_samples[j] + count[j], 1))
__global__ void k_lc(const float* __restrict__ cum_samples) {
    int i = blockIdx.x * blockDim.x + threadIdx.x;
    if (i < NN) {
        float c = cum_samples[i] + (float)g_hist[i];
        c = fmaxf(c, 1.0f);
        g_lc[i] = __logf(c);
    }
}

// ---------------------------------------------------------------------------
__device__ __forceinline__ float blockMax(float v, float* sh) {
    #pragma unroll
    for (int o = 16; o > 0; o >>= 1)
        v = fmaxf(v, __shfl_xor_sync(0xffffffffu, v, o));
    if ((threadIdx.x & 31) == 0) sh[threadIdx.x >> 5] = v;
    __syncthreads();
    if (threadIdx.x < 32) {
        float r = (threadIdx.x < (TPB / 32)) ? sh[threadIdx.x] : NEG_BIG;
        #pragma unroll
        for (int o = 4; o > 0; o >>= 1)
            r = fmaxf(r, __shfl_xor_sync(0xffffffffu, r, o));
        if (threadIdx.x == 0) sh[0] = r;
    }
    __syncthreads();
    float r = sh[0];
    __syncthreads();   // allow sh reuse by the next reduction
    return r;
}

__device__ __forceinline__ float blockSum(float v, float* sh) {
    #pragma unroll
    for (int o = 16; o > 0; o >>= 1)
        v += __shfl_xor_sync(0xffffffffu, v, o);
    if ((threadIdx.x & 31) == 0) sh[threadIdx.x >> 5] = v;
    __syncthreads();
    if (threadIdx.x < 32) {
        float r = (threadIdx.x < (TPB / 32)) ? sh[threadIdx.x] : 0.f;
        #pragma unroll
        for (int o = 4; o > 0; o >>= 1)
            r += __shfl_xor_sync(0xffffffffu, r, o);
        if (threadIdx.x == 0) sh[0] = r;
    }
    __syncthreads();
    float r = sh[0];
    __syncthreads();
    return r;
}

// One block per row: full seesaw loss for that row, all in registers/log-domain.
__global__ void __launch_bounds__(TPB) k_row(const float* __restrict__ x) {
    const int row = blockIdx.x;
    const int tid = threadIdx.x;
    const float* xr = x + (size_t)row * CC + 1;   // foreground logits, NN of them

    __shared__ float sh[8];
    __shared__ float sh_b[2];

    const int K = 10;                              // ceil(2513/256)
    float xv[K];

    float m = NEG_BIG;
    #pragma unroll
    for (int k = 0; k < K; k++) {
        int j = tid + k * TPB;
        float v = (j < NN) ? __ldg(xr + j) : NEG_BIG;
        xv[k] = v;
        m = fmaxf(m, v);
    }
    m = blockMax(m, sh);

    float s = 0.f;
    #pragma unroll
    for (int k = 0; k < K; k++) {
        int j = tid + k * TPB;
        if (j < NN) s += __expf(xv[k] - m);
    }
    float S = blockSum(s, sh);

    int label = g_labels[row];
    if (label == 0) {                  // background row: excluded from loss
        if (tid == 0) g_row_out[row] = 0.f;
        return;
    }

    if (tid == 0) {
        sh_b[0] = xr[label - 1];       // x at the positive class
        sh_b[1] = g_lc[label - 1];     // log cum_c at the positive class
    }
    __syncthreads();
    float xl   = sh_b[0];
    float lc_l = sh_b[1];

    float base = m + __logf(S);                    // logsumexp(x)
    float ls   = fmaxf(xl - base, LOG_EPS);        // log(max(self_score, EPS))

    float m2 = NEG_BIG;
    #pragma unroll
    for (int k = 0; k < K; k++) {
        int j = tid + k * TPB;
        float v2 = NEG_BIG;
        if (j < NN) {
            float lmit  = fminf(0.f, P_EXP * (__ldg(&g_lc[j]) - lc_l));
            float lcomp = fmaxf(0.f, Q_EXP * (xv[k] - base - ls));
            v2 = xv[k] + lmit + lcomp;             // == x at j == label-1
        }
        xv[k] = v2;
        m2 = fmaxf(m2, v2);
    }
    m2 = blockMax(m2, sh);

    float s2 = 0.f;
    #pragma unroll
    for (int k = 0; k < K; k++) {
        int j = tid + k * TPB;
        if (j < NN) s2 += __expf(xv[k] - m2);
    }
    float S2 = blockSum(s2, sh);

    if (tid == 0)
        g_row_out[row] = m2 + __logf(S2) - xl;     // LSE(x2) - x2[label]
}

// ---------------------------------------------------------------------------
__global__ void k_final(float* __restrict__ out) {
    __shared__ float shs[32];
    __shared__ int   shc[32];
    int tid = threadIdx.x;
    float s = 0.f;
    int   c = 0;
    for (int i = tid; i < BB; i += 1024) {
        s += g_row_out[i];
        c += (g_labels[i] != 0);
    }
    #pragma unroll
    for (int o = 16; o > 0; o >>= 1) {
        s += __shfl_xor_sync(0xffffffffu, s, o);
        c += __shfl_xor_sync(0xffffffffu, c, o);
    }
    if ((tid & 31) == 0) { shs[tid >> 5] = s; shc[tid >> 5] = c; }
    __syncthreads();
    if (tid < 32) {
        s = shs[tid];
        c = shc[tid];
        #pragma unroll
        for (int o = 16; o > 0; o >>= 1) {
            s += __shfl_xor_sync(0xffffffffu, s, o);
            c += __shfl_xor_sync(0xffffffffu, c, o);
        }
        if (tid == 0)
            out[0] = (c > 0) ? (s / (float)c) : 0.f;
    }
}

// ---------------------------------------------------------------------------
extern "C" void kernel_launch(void* const* d_in, const int* in_sizes, int n_in,
                              void* d_out, int out_size) {
    const float* x   = (const float*)d_in[0];   // input  [B, C]
    const float* t   = (const float*)d_in[1];   // target [B, C] (one-hot)
    const float* cum = (const float*)d_in[2];   // cum_samples [NN]
    (void)in_sizes; (void)n_in; (void)out_size;

    k_zero_hist<<<(NN + 255) / 256, 256>>>();
    k_labels<<<BB, TPB>>>(t);
    k_lc<<<(NN + 255) / 256, 256>>>(cum);
    k_row<<<BB, TPB>>>(x);
    k_final<<<1, 1024>>>((float*)d_out);
}